// round 10
// baseline (speedup 1.0000x reference)
#include <cuda_runtime.h>

// B3-spline UWT (a trous), J=3. x:(16,1024,1024)f32 -> (16,4,1024,1024)f32.
// Per level, fully register-resident: vertical 5-tap conv first (per-lane,
// 8 streamed row loads per warp chain of 4 rows), then horizontal 5-tap via
// warp shuffles of the vertically-smoothed values. Edge lanes act as column
// halo (outputs from interior lanes only). No smem, no barriers.
// R10: regs capped for 8 blocks/SM (full occupancy), hoisted column check.

#define HH 1024
#define WW 1024
#define BB 16
#define HW (HH * WW)

__device__ float g_buf0[BB * HW];
__device__ float g_buf1[BB * HW];

__device__ __forceinline__ int refl(int i, int L) {
    if (i < 0) i = -i;
    if (i >= L) i = 2 * L - 2 - i;
    return i;
}

__device__ __forceinline__ float4 shfl_up4(float4 v, int d) {
    float4 r;
    r.x = __shfl_up_sync(0xFFFFFFFFu, v.x, d);
    r.y = __shfl_up_sync(0xFFFFFFFFu, v.y, d);
    r.z = __shfl_up_sync(0xFFFFFFFFu, v.z, d);
    r.w = __shfl_up_sync(0xFFFFFFFFu, v.w, d);
    return r;
}
__device__ __forceinline__ float4 shfl_dn4(float4 v, int d) {
    float4 r;
    r.x = __shfl_down_sync(0xFFFFFFFFu, v.x, d);
    r.y = __shfl_down_sync(0xFFFFFFFFu, v.y, d);
    r.z = __shfl_down_sync(0xFFFFFFFFu, v.z, d);
    r.w = __shfl_down_sync(0xFFFFFFFFu, v.w, d);
    return r;
}

__device__ __forceinline__ float4 ldslow4(const float* row, int g0) {
    float4 v;
    v.x = row[refl(g0 + 0, WW)];
    v.y = row[refl(g0 + 1, WW)];
    v.z = row[refl(g0 + 2, WW)];
    v.w = row[refl(g0 + 3, WW)];
    return v;
}

__device__ __forceinline__ float4 f4axpy(float4 a, float w, float4 v) {
    a.x += w * v.x; a.y += w * v.y; a.z += w * v.z; a.w += w * v.w;
    return a;
}

template <int DIL>
__global__ __launch_bounds__(256, 8) void uwt_level(
    const float* __restrict__ in,     // (B,H,W) bstride HW
    float* __restrict__ detail,       // plane base, bstride 4*HW
    float* __restrict__ smooth,       // scratch (bstride HW) or c_J (4*HW)
    int sm_bs)
{
    constexpr int TY = 32;
    constexpr int NB = (DIL == 4) ? 2 : 1;      // halo lanes per side
    constexpr int CB = 4 * NB;                  // center offset in window t[]

    const int b    = blockIdx.z;
    const int ty0  = blockIdx.y * TY;
    const int tid  = threadIdx.x;
    const int w    = tid >> 5;
    const int lane = tid & 31;

    constexpr int TXO = 4 * (32 - 2 * NB);      // 120 / 112 output cols per warp
    const int gxv = blockIdx.x * TXO + 4 * (lane - NB);   // lane's column

    const float* base = in + b * HW;
    const float w0 = 0.0625f, w1 = 0.25f, w2 = 0.375f;
    const float W5[5] = { w0, w1, w2, w1, w0 };

    // warp's chain rows: rr = r0 + i*DIL, i=0..3 (covers [0,TY) over 8 warps)
    const int r0 = (w / DIL) * (4 * DIL) + (w % DIL);

    const bool colIn = (gxv >= 0) && (gxv + 3 < WW);      // hoisted column test

    // ---- vertical conv: stream 8 rows (r0 + (j-2)*DIL) into 4 accumulators
    float4 acc[4];
    #pragma unroll
    for (int i = 0; i < 4; i++) acc[i] = make_float4(0.f, 0.f, 0.f, 0.f);

    #pragma unroll
    for (int j = 0; j < 8; j++) {
        const int gy = refl(ty0 + r0 + (j - 2) * DIL, HH);
        const float* row = base + gy * WW;
        float4 vj = colIn ? *(const float4*)(row + gxv) : ldslow4(row, gxv);
        #pragma unroll
        for (int i = 0; i < 4; i++) {
            const int k = j - i;                // tap index for acc[i]
            if (k >= 0 && k <= 4) acc[i] = f4axpy(acc[i], W5[k], vj);
        }
    }

    // ---- horizontal conv via shuffles; interior lanes store outputs --------
    const bool doout = (lane >= NB) && (lane < 32 - NB) && (gxv < WW);
    float* dplane = detail + b * 4 * HW;
    float* splane = smooth + b * sm_bs;

    #pragma unroll
    for (int i = 0; i < 4; i++) {
        float t[4 * (2 * NB + 1)];
        *(float4*)&t[CB] = acc[i];
        #pragma unroll
        for (int d = 1; d <= NB; d++) {
            *(float4*)&t[4 * (NB - d)] = shfl_up4(acc[i], d);
            *(float4*)&t[4 * (NB + d)] = shfl_dn4(acc[i], d);
        }

        if (doout) {
            float4 sm;
            sm.x = w0 * (t[CB + 0 - 2*DIL] + t[CB + 0 + 2*DIL])
                 + w1 * (t[CB + 0 -   DIL] + t[CB + 0 +   DIL]) + w2 * t[CB + 0];
            sm.y = w0 * (t[CB + 1 - 2*DIL] + t[CB + 1 + 2*DIL])
                 + w1 * (t[CB + 1 -   DIL] + t[CB + 1 +   DIL]) + w2 * t[CB + 1];
            sm.z = w0 * (t[CB + 2 - 2*DIL] + t[CB + 2 + 2*DIL])
                 + w1 * (t[CB + 2 -   DIL] + t[CB + 2 +   DIL]) + w2 * t[CB + 2];
            sm.w = w0 * (t[CB + 3 - 2*DIL] + t[CB + 3 + 2*DIL])
                 + w1 * (t[CB + 3 -   DIL] + t[CB + 3 +   DIL]) + w2 * t[CB + 3];

            const int off = (ty0 + r0 + i * DIL) * WW + gxv;
            float4 prev = __ldg((const float4*)(base + off));  // L1 hit
            float4 dt = make_float4(prev.x - sm.x, prev.y - sm.y,
                                    prev.z - sm.z, prev.w - sm.w);

            *(float4*)(dplane + off) = dt;
            *(float4*)(splane + off) = sm;
        }
    }
}

extern "C" void kernel_launch(void* const* d_in, const int* in_sizes, int n_in,
                              void* d_out, int out_size)
{
    (void)in_sizes; (void)n_in; (void)out_size;
    const float* x = (const float*)d_in[0];
    float* out = (float*)d_out;

    float *b0, *b1;
    cudaGetSymbolAddress((void**)&b0, g_buf0);
    cudaGetSymbolAddress((void**)&b1, g_buf1);

    dim3 block(256);
    // TXO = 120 for DIL 1,2 -> 9 x-tiles; TXO = 112 for DIL 4 -> 10 x-tiles
    dim3 grid12((WW + 119) / 120, HH / 32, BB);
    dim3 grid4 ((WW + 111) / 112, HH / 32, BB);

    uwt_level<1><<<grid12, block>>>(x,  out + 0 * HW, b0, HW);
    uwt_level<2><<<grid12, block>>>(b0, out + 1 * HW, b1, HW);
    uwt_level<4><<<grid4,  block>>>(b1, out + 2 * HW, out + 3 * HW, 4 * HW);
}

// round 11
// speedup vs baseline: 1.1020x; 1.1020x over previous
#include <cuda_runtime.h>

// B3-spline UWT (a trous), J=3. x:(16,1024,1024)f32 -> (16,4,1024,1024)f32.
// Kernel A fuses levels 1+2 (w1, w2, c2) with c1 staged in smem; kernel B is
// the proven register/shuffle level-3 (R9). Deletes buf0 round-trip (~128MB).

#define HH 1024
#define WW 1024
#define BB 16
#define HW (HH * WW)

__device__ float g_c2[BB * HW];

__device__ __forceinline__ int refl(int i, int L) {
    if (i < 0) i = -i;
    if (i >= L) i = 2 * L - 2 - i;
    return i;
}

__device__ __forceinline__ float4 shfl_up4(float4 v, int d) {
    float4 r;
    r.x = __shfl_up_sync(0xFFFFFFFFu, v.x, d);
    r.y = __shfl_up_sync(0xFFFFFFFFu, v.y, d);
    r.z = __shfl_up_sync(0xFFFFFFFFu, v.z, d);
    r.w = __shfl_up_sync(0xFFFFFFFFu, v.w, d);
    return r;
}
__device__ __forceinline__ float4 shfl_dn4(float4 v, int d) {
    float4 r;
    r.x = __shfl_down_sync(0xFFFFFFFFu, v.x, d);
    r.y = __shfl_down_sync(0xFFFFFFFFu, v.y, d);
    r.z = __shfl_down_sync(0xFFFFFFFFu, v.z, d);
    r.w = __shfl_down_sync(0xFFFFFFFFu, v.w, d);
    return r;
}

__device__ __forceinline__ float4 ldslow4(const float* row, int g0) {
    float4 v;
    v.x = row[refl(g0 + 0, WW)];
    v.y = row[refl(g0 + 1, WW)];
    v.z = row[refl(g0 + 2, WW)];
    v.w = row[refl(g0 + 3, WW)];
    return v;
}

__device__ __forceinline__ float4 f4axpy(float4 a, float w, float4 v) {
    a.x += w * v.x; a.y += w * v.y; a.z += w * v.z; a.w += w * v.w;
    return a;
}

// ======================= Kernel A: levels 1+2 fused =======================
// Tile: 32 out rows x 120 out cols. c1 region: rows [-4,36), cols [-4,124)
// (= 32 float4 lanes). h1 (x horiz-conv) rows [-6,38) -> 44 smem rows.
__global__ __launch_bounds__(256, 5) void uwt_l12(
    const float* __restrict__ in,     // (B,H,W)
    float* __restrict__ out,          // w1 plane +0, w2 plane +HW (bstride 4*HW)
    float* __restrict__ c2p)          // bstride HW
{
    constexpr int TY = 32, TXO = 120;

    __shared__ float s_h1[44][128];
    __shared__ float s_c1[40][128];

    const int b    = blockIdx.z;
    const int ty0  = blockIdx.y * TY;
    const int tx0  = blockIdx.x * TXO;
    const int tid  = threadIdx.x;
    const int w    = tid >> 5;
    const int lane = tid & 31;

    const float* base = in + b * HW;
    const int  gx    = tx0 - 4 + 4 * lane;            // lane's column (c1 grid)
    const bool colIn = (gx >= 0) && (gx + 3 < WW);

    const float w0 = 0.0625f, w1 = 0.25f, w2 = 0.375f;

    // ---- Phase 1a: horizontal conv (DIL=1) of x rows -> s_h1 ----
    for (int hr = w; hr < 44; hr += 8) {
        const int gy = refl(ty0 - 6 + hr, HH);
        const float* row = base + gy * WW;
        float4 v = colIn ? *(const float4*)(row + gx) : ldslow4(row, gx);

        float t[12];
        *(float4*)&t[4] = v;
        float4 a = shfl_up4(v, 1);
        if (lane == 0)  a = ldslow4(row, gx - 4);
        *(float4*)&t[0] = a;
        float4 p = shfl_dn4(v, 1);
        if (lane == 31) p = ldslow4(row, gx + 4);
        *(float4*)&t[8] = p;

        float4 h;
        h.x = w0 * (t[2] + t[6]) + w1 * (t[3] + t[5]) + w2 * t[4];
        h.y = w0 * (t[3] + t[7]) + w1 * (t[4] + t[6]) + w2 * t[5];
        h.z = w0 * (t[4] + t[8]) + w1 * (t[5] + t[7]) + w2 * t[6];
        h.w = w0 * (t[5] + t[9]) + w1 * (t[6] + t[8]) + w2 * t[7];
        *(float4*)&s_h1[hr][4 * lane] = h;
    }
    __syncthreads();

    const bool doout = (lane >= 1) && (lane <= 30) && (gx < WW);
    float* w1p = out + b * 4 * HW;          // w1 plane
    float* w2p = out + b * 4 * HW + HW;     // w2 plane
    float* c2o = c2p + b * HW;

    // ---- Phase 1b: vertical conv (DIL=1) -> s_c1; w1 = x - c1 on tile ----
    {
        const int cr0 = 5 * w;              // c1 rows cr0..cr0+4
        float4 win[5];
        #pragma unroll
        for (int k = 0; k < 5; k++)
            win[k] = *(const float4*)&s_h1[cr0 + k][4 * lane];

        #pragma unroll
        for (int t5 = 0; t5 < 5; t5++) {
            const int cr = cr0 + t5;
            float4 c1;
            c1.x = w0 * (win[0].x + win[4].x) + w1 * (win[1].x + win[3].x) + w2 * win[2].x;
            c1.y = w0 * (win[0].y + win[4].y) + w1 * (win[1].y + win[3].y) + w2 * win[2].y;
            c1.z = w0 * (win[0].z + win[4].z) + w1 * (win[1].z + win[3].z) + w2 * win[2].z;
            c1.w = w0 * (win[0].w + win[4].w) + w1 * (win[1].w + win[3].w) + w2 * win[2].w;
            *(float4*)&s_c1[cr][4 * lane] = c1;

            if (cr >= 4 && cr < 36 && doout) {
                const int off = (ty0 + cr - 4) * WW + gx;
                float4 prev = __ldg((const float4*)(base + off));   // L1 hit
                float4 d = make_float4(prev.x - c1.x, prev.y - c1.y,
                                       prev.z - c1.z, prev.w - c1.w);
                *(float4*)(w1p + off) = d;
            }
            if (t5 < 4) {
                win[0] = win[1]; win[1] = win[2]; win[2] = win[3]; win[3] = win[4];
                win[4] = *(const float4*)&s_h1[cr0 + t5 + 5][4 * lane];
            }
        }
    }
    __syncthreads();

    // ---- Phase 2: level 2 (DIL=2): vertical from s_c1, horiz via shuffles ----
    {
        const int r0 = (w >> 1) * 8 + (w & 1);      // rows r0 + 2i, i=0..3
        float4 vwin[5];
        #pragma unroll
        for (int k = 0; k < 5; k++)
            vwin[k] = *(const float4*)&s_c1[r0 + 2 * k][4 * lane];

        #pragma unroll
        for (int i = 0; i < 4; i++) {
            const int rr = r0 + 2 * i;

            float4 vv;   // vertically convolved c1 at out-row rr, this lane's col
            vv.x = w0 * (vwin[0].x + vwin[4].x) + w1 * (vwin[1].x + vwin[3].x) + w2 * vwin[2].x;
            vv.y = w0 * (vwin[0].y + vwin[4].y) + w1 * (vwin[1].y + vwin[3].y) + w2 * vwin[2].y;
            vv.z = w0 * (vwin[0].z + vwin[4].z) + w1 * (vwin[1].z + vwin[3].z) + w2 * vwin[2].z;
            vv.w = w0 * (vwin[0].w + vwin[4].w) + w1 * (vwin[1].w + vwin[3].w) + w2 * vwin[2].w;

            float t[12];
            *(float4*)&t[4] = vv;
            *(float4*)&t[0] = shfl_up4(vv, 1);      // lanes 0/31 halo-only
            *(float4*)&t[8] = shfl_dn4(vv, 1);

            if (doout) {
                float4 c2;                          // taps +-2, +-4 floats
                c2.x = w0 * (t[0] + t[8])  + w1 * (t[2] + t[6])  + w2 * t[4];
                c2.y = w0 * (t[1] + t[9])  + w1 * (t[3] + t[7])  + w2 * t[5];
                c2.z = w0 * (t[2] + t[10]) + w1 * (t[4] + t[8])  + w2 * t[6];
                c2.w = w0 * (t[3] + t[11]) + w1 * (t[5] + t[9])  + w2 * t[7];

                const float4 c1c = vwin[2];         // c1 at (rr, this col)
                float4 d = make_float4(c1c.x - c2.x, c1c.y - c2.y,
                                       c1c.z - c2.z, c1c.w - c2.w);
                const int off = (ty0 + rr) * WW + gx;
                *(float4*)(w2p + off) = d;
                *(float4*)(c2o + off) = c2;
            }
            if (i < 3) {
                vwin[0] = vwin[1]; vwin[1] = vwin[2]; vwin[2] = vwin[3]; vwin[3] = vwin[4];
                vwin[4] = *(const float4*)&s_c1[r0 + 2 * i + 10][4 * lane];
            }
        }
    }
}

// ======================= Kernel B: level 3 (R9 engine) =======================
template <int DIL>
__global__ __launch_bounds__(256, 6) void uwt_level(
    const float* __restrict__ in,
    float* __restrict__ detail,
    float* __restrict__ smooth,
    int sm_bs)
{
    constexpr int TY = 32;
    constexpr int NB = (DIL == 4) ? 2 : 1;
    constexpr int CB = 4 * NB;

    const int b    = blockIdx.z;
    const int ty0  = blockIdx.y * TY;
    const int tid  = threadIdx.x;
    const int w    = tid >> 5;
    const int lane = tid & 31;

    constexpr int TXO = 4 * (32 - 2 * NB);
    const int tx0 = blockIdx.x * TXO;
    const int gxv = tx0 + 4 * (lane - NB);

    const float* base = in + b * HW;
    const float w0 = 0.0625f, w1 = 0.25f, w2 = 0.375f;
    const float W5[5] = { w0, w1, w2, w1, w0 };

    const int r0 = (w / DIL) * (4 * DIL) + (w % DIL);

    float4 acc[4];
    #pragma unroll
    for (int i = 0; i < 4; i++) acc[i] = make_float4(0.f, 0.f, 0.f, 0.f);

    #pragma unroll
    for (int j = 0; j < 8; j++) {
        const int gy = refl(ty0 + r0 + (j - 2) * DIL, HH);
        const float* row = base + gy * WW;
        float4 vj = (gxv >= 0 && gxv + 3 < WW) ? *(const float4*)(row + gxv)
                                               : ldslow4(row, gxv);
        #pragma unroll
        for (int i = 0; i < 4; i++) {
            const int k = j - i;
            if (k >= 0 && k <= 4) acc[i] = f4axpy(acc[i], W5[k], vj);
        }
    }

    const bool doout = (lane >= NB) && (lane < 32 - NB) && (gxv < WW);

    #pragma unroll
    for (int i = 0; i < 4; i++) {
        float t[4 * (2 * NB + 1)];
        *(float4*)&t[CB] = acc[i];
        #pragma unroll
        for (int d = 1; d <= NB; d++) {
            *(float4*)&t[4 * (NB - d)] = shfl_up4(acc[i], d);
            *(float4*)&t[4 * (NB + d)] = shfl_dn4(acc[i], d);
        }

        if (doout) {
            float4 sm;
            sm.x = w0 * (t[CB + 0 - 2*DIL] + t[CB + 0 + 2*DIL])
                 + w1 * (t[CB + 0 -   DIL] + t[CB + 0 +   DIL]) + w2 * t[CB + 0];
            sm.y = w0 * (t[CB + 1 - 2*DIL] + t[CB + 1 + 2*DIL])
                 + w1 * (t[CB + 1 -   DIL] + t[CB + 1 +   DIL]) + w2 * t[CB + 1];
            sm.z = w0 * (t[CB + 2 - 2*DIL] + t[CB + 2 + 2*DIL])
                 + w1 * (t[CB + 2 -   DIL] + t[CB + 2 +   DIL]) + w2 * t[CB + 2];
            sm.w = w0 * (t[CB + 3 - 2*DIL] + t[CB + 3 + 2*DIL])
                 + w1 * (t[CB + 3 -   DIL] + t[CB + 3 +   DIL]) + w2 * t[CB + 3];

            const int off = (ty0 + r0 + i * DIL) * WW + gxv;
            float4 prev = __ldg((const float4*)(base + off));
            float4 dt = make_float4(prev.x - sm.x, prev.y - sm.y,
                                    prev.z - sm.z, prev.w - sm.w);

            *(float4*)(detail + b * 4 * HW + off) = dt;
            *(float4*)(smooth + b * sm_bs  + off) = sm;
        }
    }
}

extern "C" void kernel_launch(void* const* d_in, const int* in_sizes, int n_in,
                              void* d_out, int out_size)
{
    (void)in_sizes; (void)n_in; (void)out_size;
    const float* x = (const float*)d_in[0];
    float* out = (float*)d_out;

    float* c2;
    cudaGetSymbolAddress((void**)&c2, g_c2);

    dim3 block(256);
    dim3 gridA((WW + 119) / 120, HH / 32, BB);   // 9 x-tiles
    dim3 gridB((WW + 111) / 112, HH / 32, BB);   // 10 x-tiles (DIL=4)

    uwt_l12<<<gridA, block>>>(x, out, c2);
    uwt_level<4><<<gridB, block>>>(c2, out + 2 * HW, out + 3 * HW, 4 * HW);
}